// round 14
// baseline (speedup 1.0000x reference)
#include <cuda_runtime.h>
#include <math.h>

#define W_   512
#define H_   512
#define HW_  (512 * 512)
#define EPS  1e-8f
#define TW   26              // output columns per warp (26 + 6 halo = 32 lanes)
#define BAND 64              // output rows per warp (70 loaded = 10 ring cycles)
#define FULLMASK 0xffffffffu

__device__ __forceinline__ float sqrt_approx(float x) {
    float r;
    asm("sqrt.approx.f32 %0, %1;" : "=f"(r) : "f"(x));
    return r;
}

// h[L] = sum_{k=0..6} v[L+k] over the warp-distributed 32-vector.
// Lanes >= 26 get garbage (shfl self) — outputs there are predicated off.
__device__ __forceinline__ float hsum7(float v) {
    float d1 = v + __shfl_down_sync(FULLMASK, v, 1);     // 2-sum
    float d2 = d1 + __shfl_down_sync(FULLMASK, d1, 2);   // 4-sum
    float r4 = __shfl_down_sync(FULLMASK, d1, 4);        // v[c+4]+v[c+5]
    float r6 = __shfl_down_sync(FULLMASK, v, 6);         // v[c+6]
    return d2 + (r4 + r6);
}

__device__ __forceinline__ float smooth_l1(float a, float b) {
    float d = a - b;
    float ad = fabsf(d);
    return (ad < 1.0f) ? 0.5f * d * d : ad - 0.5f;
}

struct Six { float a0, a1, a2, b0, b1, b2; };

__device__ __forceinline__ Six ld6(const float* __restrict__ P,
                                   const float* __restrict__ T,
                                   int off, bool ok) {
    Six s;
    s.a0 = ok ? P[off]           : 0.f;
    s.a1 = ok ? P[off + HW_]     : 0.f;
    s.a2 = ok ? P[off + 2 * HW_] : 0.f;
    s.b0 = ok ? T[off]           : 0.f;
    s.b1 = ok ? T[off + HW_]     : 0.f;
    s.b2 = ok ? T[off + 2 * HW_] : 0.f;
    return s;
}

// One row step, depth-2 load pipelining: consume nxt0 (row i), shift nxt1
// into nxt0, issue loads for row i+2 into nxt1. Horizontal 7-sum on the
// fresh row data, ring slot S into vertical sums. EMIT is compile-time:
// warm-up rows (0..5) carry no std/loss code at all.
template <int S, bool EMIT>
__device__ __forceinline__ void rowstep(
    const float* __restrict__ P, const float* __restrict__ T,
    int gx, bool okx, bool out_ok, int oy0,
    int& i, Six& nxt0, Six& nxt1, float (&ring)[4][7], float (&vs)[4],
    float& acc, float inv_n)
{
    Six cur = nxt0;
    nxt0 = nxt1;

    {   // prefetch row i+2 (tail prefetches discarded; guard predicates OOB)
        const int gy2 = oy0 - 1 + i;
        const bool ok2 = okx && (gy2 >= 0) && (gy2 < H_);
        nxt1 = ld6(P, T, (gy2 << 9) + gx, ok2);
    }

    float h0, h1, h2, h3;
    {
        float v  = cur.a0 + cur.a1 + cur.a2;
        float v2 = fmaf(cur.a0, cur.a0, fmaf(cur.a1, cur.a1, cur.a2 * cur.a2));
        h0 = hsum7(v);
        h1 = hsum7(v2);
    }
    {
        float v  = cur.b0 + cur.b1 + cur.b2;
        float v2 = fmaf(cur.b0, cur.b0, fmaf(cur.b1, cur.b1, cur.b2 * cur.b2));
        h2 = hsum7(v);
        h3 = hsum7(v2);
    }

    vs[0] += h0 - ring[0][S]; ring[0][S] = h0;
    vs[1] += h1 - ring[1][S]; ring[1][S] = h1;
    vs[2] += h2 - ring[2][S]; ring[2][S] = h2;
    vs[3] += h3 - ring[3][S]; ring[3][S] = h3;

    if (EMIT) {
        float mp = vs[0] * inv_n;
        float sp = sqrt_approx(fmaf(-mp, mp, vs[1] * inv_n) + EPS);
        float mt = vs[2] * inv_n;
        float st = sqrt_approx(fmaf(-mt, mt, vs[3] * inv_n) + EPS);
        float f = smooth_l1(sp, st);
        acc += out_ok ? f : 0.f;
    }
    i++;
}

__global__ __launch_bounds__(64, 12)
void dist_loss_kernel(const float* __restrict__ pred,
                      const float* __restrict__ tgt,
                      float* __restrict__ out)
{
    const int L  = threadIdx.x & 31;
    const int w  = threadIdx.x >> 5;
    const int x0 = blockIdx.x * TW;
    const int oy0 = (blockIdx.y << 7) + w * BAND;     // warp's first output row
    const size_t bofs = (size_t)blockIdx.z * 3 * HW_;
    const float* P = pred + bofs;
    const float* T = tgt + bofs;

    const int gx = x0 - 3 + L;                        // halo-inclusive column
    const bool okx = (gx >= 0) && (gx < W_);
    const bool out_ok = (L < TW) && ((x0 + L) < W_);

    const float inv_n = 1.0f / 147.0f;

    float ring[4][7];
    float vs[4];
#pragma unroll
    for (int a = 0; a < 4; a++) {
        vs[a] = 0.f;
#pragma unroll
        for (int j = 0; j < 7; j++) ring[a][j] = 0.f;
    }

    float acc = 0.f;
    int i = 0;

    // prime the 2-deep pipeline with rows 0 and 1
    Six nxt0, nxt1;
    {
        const int gyA = oy0 - 3;
        const int gyB = oy0 - 2;
        nxt0 = ld6(P, T, (gyA << 9) + gx, okx && (gyA >= 0));
        nxt1 = ld6(P, T, (gyB << 9) + gx, okx && (gyB >= 0));
    }

    // 70 rows: 6 warm-up (slots 0..5, EMIT=false), 1 emit (slot 6),
    // then 9 full ring cycles of 7 emitting rows. 6 + 1 + 63 = 70.
    rowstep<0, false>(P, T, gx, okx, out_ok, oy0, i, nxt0, nxt1, ring, vs, acc, inv_n);
    rowstep<1, false>(P, T, gx, okx, out_ok, oy0, i, nxt0, nxt1, ring, vs, acc, inv_n);
    rowstep<2, false>(P, T, gx, okx, out_ok, oy0, i, nxt0, nxt1, ring, vs, acc, inv_n);
    rowstep<3, false>(P, T, gx, okx, out_ok, oy0, i, nxt0, nxt1, ring, vs, acc, inv_n);
    rowstep<4, false>(P, T, gx, okx, out_ok, oy0, i, nxt0, nxt1, ring, vs, acc, inv_n);
    rowstep<5, false>(P, T, gx, okx, out_ok, oy0, i, nxt0, nxt1, ring, vs, acc, inv_n);
    rowstep<6, true >(P, T, gx, okx, out_ok, oy0, i, nxt0, nxt1, ring, vs, acc, inv_n);
#pragma unroll 1
    for (int c = 0; c < 9; c++) {
        rowstep<0, true>(P, T, gx, okx, out_ok, oy0, i, nxt0, nxt1, ring, vs, acc, inv_n);
        rowstep<1, true>(P, T, gx, okx, out_ok, oy0, i, nxt0, nxt1, ring, vs, acc, inv_n);
        rowstep<2, true>(P, T, gx, okx, out_ok, oy0, i, nxt0, nxt1, ring, vs, acc, inv_n);
        rowstep<3, true>(P, T, gx, okx, out_ok, oy0, i, nxt0, nxt1, ring, vs, acc, inv_n);
        rowstep<4, true>(P, T, gx, okx, out_ok, oy0, i, nxt0, nxt1, ring, vs, acc, inv_n);
        rowstep<5, true>(P, T, gx, okx, out_ok, oy0, i, nxt0, nxt1, ring, vs, acc, inv_n);
        rowstep<6, true>(P, T, gx, okx, out_ok, oy0, i, nxt0, nxt1, ring, vs, acc, inv_n);
    }

    // warp + block reduce (2 warps)
#pragma unroll
    for (int o = 16; o > 0; o >>= 1)
        acc += __shfl_xor_sync(FULLMASK, acc, o);

    __shared__ float ws[2];
    if (L == 0) ws[w] = acc;
    __syncthreads();
    if (threadIdx.x == 0) {
        float s = ws[0] + ws[1];
        atomicAdd(out, s * (1.0f / (16.0f * 512.0f * 512.0f)));
    }
}

extern "C" void kernel_launch(void* const* d_in, const int* in_sizes, int n_in,
                              void* d_out, int out_size)
{
    const float* pred = (const float*)d_in[0];
    const float* tgt  = (const float*)d_in[1];
    float* out = (float*)d_out;

    cudaMemsetAsync(out, 0, sizeof(float));

    dim3 block(64, 1, 1);
    // x: 20 tiles, y: 512 / (64*2) = 4, z: 16  -> 1280 CTAs (2 warps each)
    dim3 grid((W_ + TW - 1) / TW, H_ / (BAND * 2), 16);
    dist_loss_kernel<<<grid, block>>>(pred, tgt, out);
}

// round 15
// speedup vs baseline: 1.0605x; 1.0605x over previous
#include <cuda_runtime.h>
#include <math.h>

#define W_   512
#define H_   512
#define HW_  (512 * 512)
#define EPS  1e-8f
#define TW   26              // output columns per warp (26 + 6 halo = 32 lanes)
#define FULLMASK 0xffffffffu

__device__ __forceinline__ float sqrt_approx(float x) {
    float r;
    asm("sqrt.approx.f32 %0, %1;" : "=f"(r) : "f"(x));
    return r;
}

// h[L] = sum_{k=0..6} v[L+k] over the warp-distributed 32-vector.
// Lanes >= 26 get garbage (shfl self) — outputs there are predicated off.
__device__ __forceinline__ float hsum7(float v) {
    float d1 = v + __shfl_down_sync(FULLMASK, v, 1);     // 2-sum
    float d2 = d1 + __shfl_down_sync(FULLMASK, d1, 2);   // 4-sum
    float r4 = __shfl_down_sync(FULLMASK, d1, 4);        // v[c+4]+v[c+5]
    float r6 = __shfl_down_sync(FULLMASK, v, 6);         // v[c+6]
    return d2 + (r4 + r6);
}

__device__ __forceinline__ float smooth_l1(float a, float b) {
    float d = a - b;
    float ad = fabsf(d);
    return (ad < 1.0f) ? 0.5f * d * d : ad - 0.5f;
}

// One row's raw data + validity mask (0.0 or 1.0)
struct Seven { float a0, a1, a2, b0, b1, b2, m; };

// Unconditional load from clamped row; mask applied later at channel-reduce.
__device__ __forceinline__ Seven ld7(const float* __restrict__ P,
                                     const float* __restrict__ T,
                                     int gy, float okx_f) {
    int gyc = gy < 0 ? 0 : (gy > (H_ - 1) ? (H_ - 1) : gy);  // clamp to image
    int off = gyc << 9;
    Seven s;
    s.a0 = P[off];
    s.a1 = P[off + HW_];
    s.a2 = P[off + 2 * HW_];
    s.b0 = T[off];
    s.b1 = T[off + HW_];
    s.b2 = T[off + 2 * HW_];
    s.m  = ((unsigned)gy < (unsigned)H_) ? okx_f : 0.f;
    return s;
}

// One row step. A holds row i (consume), B holds row i+1 (in flight).
// Prefetch row i+2 into A (the just-freed buffer); caller swaps A/B per row.
// Horizontal 7-sum on fresh masked data, ring slot S into vertical sums.
// EMIT is compile-time: warm-up rows carry no std/loss code.
template <int S, bool EMIT>
__device__ __forceinline__ void rowstep(
    const float* __restrict__ P, const float* __restrict__ T,
    float okx_f, bool out_ok, int oy0,
    int& i, Seven& A, Seven& B, float (&ring)[4][7], float (&vs)[4],
    float& acc, float inv_n)
{
    Seven cur = A;
    A = ld7(P, T, oy0 - 1 + i, okx_f);   // row i+2 into freed buffer
    (void)B;                              // B (row i+1) consumed next call

    float h0, h1, h2, h3;
    {
        float v  = (cur.a0 + cur.a1 + cur.a2) * cur.m;
        float v2 = fmaf(cur.a0, cur.a0, fmaf(cur.a1, cur.a1, cur.a2 * cur.a2)) * cur.m;
        h0 = hsum7(v);
        h1 = hsum7(v2);
    }
    {
        float v  = (cur.b0 + cur.b1 + cur.b2) * cur.m;
        float v2 = fmaf(cur.b0, cur.b0, fmaf(cur.b1, cur.b1, cur.b2 * cur.b2)) * cur.m;
        h2 = hsum7(v);
        h3 = hsum7(v2);
    }

    vs[0] += h0 - ring[0][S]; ring[0][S] = h0;
    vs[1] += h1 - ring[1][S]; ring[1][S] = h1;
    vs[2] += h2 - ring[2][S]; ring[2][S] = h2;
    vs[3] += h3 - ring[3][S]; ring[3][S] = h3;

    if (EMIT) {
        float mp = vs[0] * inv_n;
        float sp = sqrt_approx(fmaf(-mp, mp, vs[1] * inv_n) + EPS);
        float mt = vs[2] * inv_n;
        float st = sqrt_approx(fmaf(-mt, mt, vs[3] * inv_n) + EPS);
        float f = smooth_l1(sp, st);
        acc += out_ok ? f : 0.f;
    }
    i++;
}

// Two rows per macro-step with buffer parity swap (kills the nxt0=nxt1 shift)
#define ROW2(Sa, Ea, Sb, Eb) \
    rowstep<Sa, Ea>(P, T, okx_f, out_ok, oy0, i, nA, nB, ring, vs, acc, inv_n); \
    rowstep<Sb, Eb>(P, T, okx_f, out_ok, oy0, i, nB, nA, ring, vs, acc, inv_n);

__global__ __launch_bounds__(128, 6)
void dist_loss_kernel(const float* __restrict__ pred,
                      const float* __restrict__ tgt,
                      float* __restrict__ out)
{
    const int L  = threadIdx.x & 31;
    const int w  = threadIdx.x >> 5;
    const int x0 = blockIdx.x * TW;
    const int oy0 = (blockIdx.y << 7) + (w << 5);     // warp's first output row
    const size_t bofs = (size_t)blockIdx.z * 3 * HW_;

    const int gx = x0 - 3 + L;                        // halo-inclusive column
    const bool okx = (gx >= 0) && (gx < W_);
    const float okx_f = okx ? 1.f : 0.f;
    const int gxs = okx ? gx : 0;                     // clamped for addressing
    const float* P = pred + bofs + gxs;
    const float* T = tgt  + bofs + gxs;

    const bool out_ok = (L < TW) && ((x0 + L) < W_);
    const float inv_n = 1.0f / 147.0f;

    float ring[4][7];
    float vs[4];
#pragma unroll
    for (int a = 0; a < 4; a++) {
        vs[a] = 0.f;
#pragma unroll
        for (int j = 0; j < 7; j++) ring[a][j] = 0.f;
    }

    float acc = 0.f;
    int i = 0;

    // prime the 2-deep pipeline with rows 0 and 1
    Seven nA = ld7(P, T, oy0 - 3, okx_f);
    Seven nB = ld7(P, T, oy0 - 2, okx_f);

    // 38 rows: 6 warm-up (slots 0..5, EMIT=false), then 32 emitting rows.
    ROW2(0, false, 1, false)
    ROW2(2, false, 3, false)
    ROW2(4, false, 5, false)
    ROW2(6, true,  0, true)
#pragma unroll 1
    for (int c = 0; c < 2; c++) {        // 14 rows per iter, 28 total
        ROW2(1, true, 2, true)
        ROW2(3, true, 4, true)
        ROW2(5, true, 6, true)
        ROW2(0, true, 1, true)
        ROW2(2, true, 3, true)
        ROW2(4, true, 5, true)
        ROW2(6, true, 0, true)
    }
    ROW2(1, true, 2, true)               // rows 36, 37

    // warp + block reduce
#pragma unroll
    for (int o = 16; o > 0; o >>= 1)
        acc += __shfl_xor_sync(FULLMASK, acc, o);

    __shared__ float ws[4];
    if (L == 0) ws[w] = acc;
    __syncthreads();
    if (threadIdx.x == 0) {
        float s = ws[0] + ws[1] + ws[2] + ws[3];
        atomicAdd(out, s * (1.0f / (16.0f * 512.0f * 512.0f)));
    }
}

extern "C" void kernel_launch(void* const* d_in, const int* in_sizes, int n_in,
                              void* d_out, int out_size)
{
    const float* pred = (const float*)d_in[0];
    const float* tgt  = (const float*)d_in[1];
    float* out = (float*)d_out;

    cudaMemsetAsync(out, 0, sizeof(float));

    dim3 block(128, 1, 1);
    dim3 grid((W_ + TW - 1) / TW, H_ / 128, 16);   // 20 x 4 x 16 = 1280 CTAs
    dist_loss_kernel<<<grid, block>>>(pred, tgt, out);
}